// round 5
// baseline (speedup 1.0000x reference)
#include <cuda_runtime.h>
#include <cuda_bf16.h>
#include <cstdint>

#define N_NODES 20000
#define N_EDGES 320000
#define ET      (N_EDGES + N_NODES)   // 340000
#define GCN_IN  256
#define C1      128
#define H1      5
#define F1      (H1*C1)               // 640
#define C2      128
#define H2      3
#define F2      (H2*C2)               // 384
#define N_BBOX  4096
#define NB_SCAN ((N_NODES + 1023) / 1024)   // 20

// ---------------- scratch ---------------------------------------------------
__device__ int   g_is64;
__device__ int   g_cnt[N_NODES];
__device__ int   g_cur[N_NODES];
__device__ int   g_claim[N_NODES];
__device__ int   g_off[N_NODES + 1];
__device__ int   g_src[ET];
__device__ int   g_bsum[32];
__device__ int   g_bpre[32];
__device__ float g_h1[(size_t)N_NODES * F1];
__device__ float g_o1[(size_t)N_NODES * F1];
__device__ float g_h2[(size_t)N_NODES * F2];
__device__ float g_as1[N_NODES * H1];
__device__ float g_ad1[N_NODES * H1];
__device__ float g_as2[N_NODES * H2];
__device__ float g_ad2[N_NODES * H2];
__device__ float g_rinv1[N_NODES * H1];
__device__ float g_rinv2[N_NODES * H2];
__device__ float g_alpha1[(size_t)ET * H1];
__device__ float g_alpha2[(size_t)ET * H2];

__device__ __forceinline__ float leaky(float x, float s) {
    return x >= 0.f ? x : s * x;
}
__device__ __forceinline__ int load_idx(const void* p, long long i) {
    return g_is64 ? (int)((const long long*)p)[i] : ((const int*)p)[i];
}
__device__ __forceinline__ uint32_t f2tf32(float x) {
    uint32_t u;
    asm("cvt.rna.tf32.f32 %0, %1;" : "=r"(u) : "f"(x));
    return u;
}

// ---------------- dtype sniff -----------------------------------------------
__global__ void k_detect(const void* ei) {
    const int* p = (const int*)ei;
    int nz = 0;
    #pragma unroll
    for (int i = 0; i < 64; i++) nz |= p[2 * i + 1];
    g_is64 = (nz == 0) ? 1 : 0;
}

// ---------------- CSR build -------------------------------------------------
__global__ void k_zero() {
    int i = blockIdx.x * blockDim.x + threadIdx.x;
    if (i < N_NODES) { g_cnt[i] = 0; g_cur[i] = 0; g_claim[i] = 0; }
}

__global__ void k_hist(const void* __restrict__ ei) {
    int e = blockIdx.x * blockDim.x + threadIdx.x;
    if (e >= ET) return;
    int dst = (e < N_EDGES) ? load_idx(ei, (long long)N_EDGES + e) : (e - N_EDGES);
    atomicAdd(&g_cnt[dst], 1);
}

__global__ void k_scan1() {
    __shared__ int ws[32];
    int tid = threadIdx.x, lane = tid & 31, wid = tid >> 5;
    int i = blockIdx.x * 1024 + tid;
    int v = (i < N_NODES) ? g_cnt[i] : 0;
    int x = v;
    #pragma unroll
    for (int o = 1; o < 32; o <<= 1) {
        int y = __shfl_up_sync(~0u, x, o);
        if (lane >= o) x += y;
    }
    if (lane == 31) ws[wid] = x;
    __syncthreads();
    if (wid == 0) {
        int w = ws[lane];
        #pragma unroll
        for (int o = 1; o < 32; o <<= 1) {
            int y = __shfl_up_sync(~0u, w, o);
            if (lane >= o) w += y;
        }
        ws[lane] = w;
    }
    __syncthreads();
    int incl = x + (wid > 0 ? ws[wid - 1] : 0);
    if (i < N_NODES) g_off[i + 1] = incl;
    if (tid == 1023) g_bsum[blockIdx.x] = incl;
}

__global__ void k_scan2() {
    int lane = threadIdx.x;
    int v = (lane < NB_SCAN) ? g_bsum[lane] : 0;
    int x = v;
    #pragma unroll
    for (int o = 1; o < 32; o <<= 1) {
        int y = __shfl_up_sync(~0u, x, o);
        if (lane >= o) x += y;
    }
    g_bpre[lane] = x - v;
}

__global__ void k_scan3() {
    int i = blockIdx.x * 1024 + threadIdx.x;
    if (i == 0) g_off[0] = 0;
    if (i < N_NODES) g_off[i + 1] += g_bpre[blockIdx.x];
}

__global__ void k_scatter(const void* __restrict__ ei) {
    int e = blockIdx.x * blockDim.x + threadIdx.x;
    if (e >= ET) return;
    int src, dst;
    if (e < N_EDGES) {
        src = load_idx(ei, e);
        dst = load_idx(ei, (long long)N_EDGES + e);
    } else {
        src = dst = e - N_EDGES;
    }
    int p = g_off[dst] + atomicAdd(&g_cur[dst], 1);
    g_src[p] = src;
}

// ---------------- TF32 tensor-core GEMM, register double-buffered ----------
// C[M,N] = A[M,K] @ B[K,N]; BM=128 BN=64 BK=32; 8 warps, warp tile 32x32.
template<int MODE>
__global__ void gemm_tf32(const float* __restrict__ Ain, const float* __restrict__ B) {
    const int M = N_NODES;
    const int N = (MODE == 0) ? F1 : F2;
    const int K = (MODE == 0) ? GCN_IN : F1;
    const float* A = (MODE == 0) ? Ain : (const float*)g_o1;
    float* C = (MODE == 0) ? g_h1 : g_h2;

    const int BM = 128, BN = 64, BK = 32;
    __shared__ uint32_t As[BK][BM + 4];   // [k][m], tf32 bits
    __shared__ uint32_t Bs[BK][BN + 4];   // [k][n], tf32 bits

    int tid = threadIdx.x;
    int lane = tid & 31, warp = tid >> 5;
    int warp_m = (warp & 3) * 32;
    int warp_n = (warp >> 2) * 32;
    int rb = blockIdx.y * BM, cb = blockIdx.x * BN;
    int grp = lane >> 2, sub = lane & 3;

    // per-thread load map
    const int aR = tid >> 3;           // 0..31 (+p*32)
    const int aC = (tid & 7) * 4;      // k-col
    const int bR = tid >> 4;           // 0..15 (+p*16)
    const int bC = (tid & 15) * 4;

    float4 ra[4], rbuf[2];

    auto loadA = [&](int k0) {
        #pragma unroll
        for (int p = 0; p < 4; p++) {
            int r = p * 32 + aR;
            ra[p] = make_float4(0, 0, 0, 0);
            if (rb + r < M)
                ra[p] = *reinterpret_cast<const float4*>(A + (size_t)(rb + r) * K + k0 + aC);
        }
    };
    auto loadB = [&](int k0) {
        #pragma unroll
        for (int p = 0; p < 2; p++) {
            int r = p * 16 + bR;
            rbuf[p] = *reinterpret_cast<const float4*>(B + (size_t)(k0 + r) * N + cb + bC);
        }
    };
    auto stageA = [&]() {
        #pragma unroll
        for (int p = 0; p < 4; p++) {
            int r = p * 32 + aR;
            As[aC + 0][r] = f2tf32(ra[p].x);
            As[aC + 1][r] = f2tf32(ra[p].y);
            As[aC + 2][r] = f2tf32(ra[p].z);
            As[aC + 3][r] = f2tf32(ra[p].w);
        }
    };
    auto stageB = [&]() {
        #pragma unroll
        for (int p = 0; p < 2; p++) {
            int r = p * 16 + bR;
            Bs[r][bC + 0] = f2tf32(rbuf[p].x);
            Bs[r][bC + 1] = f2tf32(rbuf[p].y);
            Bs[r][bC + 2] = f2tf32(rbuf[p].z);
            Bs[r][bC + 3] = f2tf32(rbuf[p].w);
        }
    };

    float acc[2][4][4];
    #pragma unroll
    for (int i = 0; i < 2; i++)
        #pragma unroll
        for (int j = 0; j < 4; j++)
            #pragma unroll
            for (int q = 0; q < 4; q++) acc[i][j][q] = 0.f;

    loadA(0); loadB(0);

    for (int k0 = 0; k0 < K; k0 += BK) {
        stageA(); stageB();
        __syncthreads();
        if (k0 + BK < K) { loadA(k0 + BK); loadB(k0 + BK); }  // in-flight during mma

        #pragma unroll
        for (int kk = 0; kk < 4; kk++) {
            int kb = kk * 8;
            uint32_t a[2][4];
            #pragma unroll
            for (int mt = 0; mt < 2; mt++) {
                int mr = warp_m + mt * 16;
                a[mt][0] = As[kb + sub    ][mr + grp    ];
                a[mt][1] = As[kb + sub    ][mr + grp + 8];
                a[mt][2] = As[kb + sub + 4][mr + grp    ];
                a[mt][3] = As[kb + sub + 4][mr + grp + 8];
            }
            #pragma unroll
            for (int nt = 0; nt < 4; nt++) {
                int nc = warp_n + nt * 8;
                uint32_t b0 = Bs[kb + sub    ][nc + grp];
                uint32_t b1 = Bs[kb + sub + 4][nc + grp];
                #pragma unroll
                for (int mt = 0; mt < 2; mt++) {
                    asm volatile(
                        "mma.sync.aligned.m16n8k8.row.col.f32.tf32.tf32.f32 "
                        "{%0,%1,%2,%3}, {%4,%5,%6,%7}, {%8,%9}, {%0,%1,%2,%3};"
                        : "+f"(acc[mt][nt][0]), "+f"(acc[mt][nt][1]),
                          "+f"(acc[mt][nt][2]), "+f"(acc[mt][nt][3])
                        : "r"(a[mt][0]), "r"(a[mt][1]), "r"(a[mt][2]), "r"(a[mt][3]),
                          "r"(b0), "r"(b1));
                }
            }
        }
        __syncthreads();
    }

    #pragma unroll
    for (int mt = 0; mt < 2; mt++) {
        int r0 = rb + warp_m + mt * 16 + grp;
        #pragma unroll
        for (int nt = 0; nt < 4; nt++) {
            int c0 = cb + warp_n + nt * 8 + 2 * sub;
            if (r0 < M) {
                C[(size_t)r0 * N + c0]     = acc[mt][nt][0];
                C[(size_t)r0 * N + c0 + 1] = acc[mt][nt][1];
            }
            if (r0 + 8 < M) {
                C[(size_t)(r0 + 8) * N + c0]     = acc[mt][nt][2];
                C[(size_t)(r0 + 8) * N + c0 + 1] = acc[mt][nt][3];
            }
        }
    }
}

// ---------------- attention logits ------------------------------------------
template<int MODE>
__global__ void k_att(const float* __restrict__ asrc, const float* __restrict__ adst) {
    const int H = (MODE == 0) ? H1 : H2;
    const float* h = (MODE == 0) ? (const float*)g_h1 : (const float*)g_h2;
    float* oas = (MODE == 0) ? g_as1 : g_as2;
    float* oad = (MODE == 0) ? g_ad1 : g_ad2;
    int w = (blockIdx.x * blockDim.x + threadIdx.x) >> 5;
    int lane = threadIdx.x & 31;
    if (w >= N_NODES * H) return;
    int n = w / H, hh = w % H;
    const float* hp = h + (size_t)n * (H * 128) + hh * 128;
    const float* ap = asrc + hh * 128;
    const float* bp = adst + hh * 128;
    float s = 0.f, d = 0.f;
    #pragma unroll
    for (int j = 0; j < 4; j++) {
        float v = hp[lane + 32 * j];
        s += v * ap[lane + 32 * j];
        d += v * bp[lane + 32 * j];
    }
    #pragma unroll
    for (int o = 16; o; o >>= 1) {
        s += __shfl_xor_sync(~0u, s, o);
        d += __shfl_xor_sync(~0u, d, o);
    }
    if (lane == 0) { oas[w] = s; oad[w] = d; }
}

// ---------------- segment softmax: store exp + 1/denom (2 passes) ----------
template<int H>
__device__ __forceinline__ void softmax_node(int n, const float* as_, const float* ad_,
                                             float* alpha, float* rinvg, int lane) {
    int beg = g_off[n], end = g_off[n + 1];
    float ad[H], m[H], dsum[H];
    #pragma unroll
    for (int h = 0; h < H; h++) { ad[h] = ad_[n * H + h]; m[h] = -1e30f; dsum[h] = 0.f; }
    for (int i = beg + lane; i < end; i += 32) {
        int s = g_src[i];
        #pragma unroll
        for (int h = 0; h < H; h++) {
            float e = leaky(as_[s * H + h] + ad[h], 0.2f);
            alpha[(size_t)i * H + h] = e;
            m[h] = fmaxf(m[h], e);
        }
    }
    #pragma unroll
    for (int h = 0; h < H; h++)
        #pragma unroll
        for (int o = 16; o; o >>= 1) m[h] = fmaxf(m[h], __shfl_xor_sync(~0u, m[h], o));
    for (int i = beg + lane; i < end; i += 32) {
        #pragma unroll
        for (int h = 0; h < H; h++) {
            float ex = expf(alpha[(size_t)i * H + h] - m[h]);
            alpha[(size_t)i * H + h] = ex;
            dsum[h] += ex;
        }
    }
    #pragma unroll
    for (int h = 0; h < H; h++)
        #pragma unroll
        for (int o = 16; o; o >>= 1) dsum[h] += __shfl_xor_sync(~0u, dsum[h], o);
    if (lane == 0)
        #pragma unroll
        for (int h = 0; h < H; h++) rinvg[n * H + h] = 1.f / (dsum[h] + 1e-16f);
}

__global__ void k_softmax1() {
    int n = (blockIdx.x * blockDim.x + threadIdx.x) >> 5;
    int lane = threadIdx.x & 31;
    if (n >= N_NODES) return;
    softmax_node<H1>(n, g_as1, g_ad1, g_alpha1, g_rinv1, lane);
}

// layer-2 softmax only for bbox nodes (deduped via claim flag)
__global__ void k_softmax2(const void* __restrict__ bbox) {
    int wi = (blockIdx.x * blockDim.x + threadIdx.x) >> 5;
    int lane = threadIdx.x & 31;
    if (wi >= N_BBOX) return;
    int n = load_idx(bbox, wi);
    int claimed = 0;
    if (lane == 0) claimed = atomicExch(&g_claim[n], 1);
    claimed = __shfl_sync(~0u, claimed, 0);
    if (claimed) return;
    softmax_node<H2>(n, g_as2, g_ad2, g_alpha2, g_rinv2, lane);
}

// ---------------- layer-1 aggregation, 4x edge unroll -----------------------
__global__ void k_agg1(const float* __restrict__ b1) {
    int n = blockIdx.x;
    int t = threadIdx.x;
    int beg = g_off[n], end = g_off[n + 1];
    float acc[H1] = {0.f, 0.f, 0.f, 0.f, 0.f};
    int i = beg;
    for (; i + 4 <= end; i += 4) {
        int s0 = g_src[i], s1 = g_src[i + 1], s2 = g_src[i + 2], s3 = g_src[i + 3];
        const float* p0 = g_h1 + (size_t)s0 * F1;
        const float* p1 = g_h1 + (size_t)s1 * F1;
        const float* p2 = g_h1 + (size_t)s2 * F1;
        const float* p3 = g_h1 + (size_t)s3 * F1;
        float al[4][H1];
        #pragma unroll
        for (int e = 0; e < 4; e++)
            #pragma unroll
            for (int h = 0; h < H1; h++) al[e][h] = g_alpha1[(size_t)(i + e) * H1 + h];
        #pragma unroll
        for (int h = 0; h < H1; h++) {
            acc[h] += al[0][h] * p0[h * 128 + t];
            acc[h] += al[1][h] * p1[h * 128 + t];
            acc[h] += al[2][h] * p2[h * 128 + t];
            acc[h] += al[3][h] * p3[h * 128 + t];
        }
    }
    for (; i < end; i++) {
        int s = g_src[i];
        const float* hp = g_h1 + (size_t)s * F1;
        #pragma unroll
        for (int h = 0; h < H1; h++)
            acc[h] += g_alpha1[(size_t)i * H1 + h] * hp[h * 128 + t];
    }
    #pragma unroll
    for (int h = 0; h < H1; h++) {
        float v = acc[h] * g_rinv1[n * H1 + h] + b1[h * 128 + t];
        g_o1[(size_t)n * F1 + h * 128 + t] = leaky(v, 0.01f);
    }
}

// ---------------- layer-2 aggregation: bbox entries, 4x unroll --------------
__global__ void k_agg2(const void* __restrict__ bbox, const float* __restrict__ b2,
                       float* __restrict__ out) {
    int bi = blockIdx.x;
    int t = threadIdx.x;
    int n = load_idx(bbox, bi);
    int beg = g_off[n], end = g_off[n + 1];
    float acc[H2] = {0.f, 0.f, 0.f};
    int e = beg;
    for (; e + 4 <= end; e += 4) {
        int s0 = g_src[e], s1 = g_src[e + 1], s2 = g_src[e + 2], s3 = g_src[e + 3];
        const float* p0 = g_h2 + (size_t)s0 * F2;
        const float* p1 = g_h2 + (size_t)s1 * F2;
        const float* p2 = g_h2 + (size_t)s2 * F2;
        const float* p3 = g_h2 + (size_t)s3 * F2;
        float al[4][H2];
        #pragma unroll
        for (int q = 0; q < 4; q++)
            #pragma unroll
            for (int h = 0; h < H2; h++) al[q][h] = g_alpha2[(size_t)(e + q) * H2 + h];
        #pragma unroll
        for (int h = 0; h < H2; h++) {
            acc[h] += al[0][h] * p0[h * 128 + t];
            acc[h] += al[1][h] * p1[h * 128 + t];
            acc[h] += al[2][h] * p2[h * 128 + t];
            acc[h] += al[3][h] * p3[h * 128 + t];
        }
    }
    for (; e < end; e++) {
        int s = g_src[e];
        const float* hp = g_h2 + (size_t)s * F2;
        #pragma unroll
        for (int h = 0; h < H2; h++)
            acc[h] += g_alpha2[(size_t)e * H2 + h] * hp[h * 128 + t];
    }
    float v = (acc[0] * g_rinv2[n * H2 + 0] +
               acc[1] * g_rinv2[n * H2 + 1] +
               acc[2] * g_rinv2[n * H2 + 2]) * (1.f / 3.f) + b2[t];
    out[(size_t)bi * 128 + t] = leaky(v, 0.01f);
}

// ---------------- launch ----------------------------------------------------
extern "C" void kernel_launch(void* const* d_in, const int* in_sizes, int n_in,
                              void* d_out, int out_size) {
    const float *x = nullptr, *W1 = nullptr, *W2 = nullptr, *b1 = nullptr, *b2 = nullptr;
    const float *att_src1 = nullptr, *att_dst1 = nullptr;
    const float *att_src2 = nullptr, *att_dst2 = nullptr;
    const void *ei = nullptr, *bbox = nullptr;
    int n640 = 0, n384 = 0;
    for (int i = 0; i < n_in; i++) {
        switch (in_sizes[i]) {
            case N_NODES * GCN_IN: x    = (const float*)d_in[i]; break;
            case 2 * N_EDGES:      ei   = d_in[i]; break;
            case N_BBOX:           bbox = d_in[i]; break;
            case GCN_IN * F1:      W1   = (const float*)d_in[i]; break;
            case F1 * F2:          W2   = (const float*)d_in[i]; break;
            case C2:               b2   = (const float*)d_in[i]; break;
            case F1:
                if      (n640 == 0) att_src1 = (const float*)d_in[i];
                else if (n640 == 1) att_dst1 = (const float*)d_in[i];
                else                b1       = (const float*)d_in[i];
                n640++; break;
            case F2:
                if (n384 == 0) att_src2 = (const float*)d_in[i];
                else           att_dst2 = (const float*)d_in[i];
                n384++; break;
            default: break;
        }
    }
    float* out = (float*)d_out;

    k_detect<<<1, 1>>>(ei);                                  // 1
    k_zero<<<(N_NODES + 255) / 256, 256>>>();                // 2
    k_hist<<<(ET + 255) / 256, 256>>>(ei);                   // 3
    {                                                        // 4 (profiled slot)
        dim3 g(F1 / 64, (N_NODES + 127) / 128);
        gemm_tf32<0><<<g, 256>>>(x, W1);
    }
    k_scan1<<<NB_SCAN, 1024>>>();                            // 5
    k_scan2<<<1, 32>>>();                                    // 6
    k_scan3<<<NB_SCAN, 1024>>>();                            // 7
    k_scatter<<<(ET + 255) / 256, 256>>>(ei);                // 8
    k_att<0><<<(N_NODES * H1 * 32 + 255) / 256, 256>>>(att_src1, att_dst1);
    k_softmax1<<<(N_NODES * 32 + 255) / 256, 256>>>();
    k_agg1<<<N_NODES, 128>>>(b1);

    {
        dim3 g(F2 / 64, (N_NODES + 127) / 128);
        gemm_tf32<1><<<g, 256>>>(nullptr, W2);
    }
    k_att<1><<<(N_NODES * H2 * 32 + 255) / 256, 256>>>(att_src2, att_dst2);
    k_softmax2<<<(N_BBOX * 32 + 255) / 256, 256>>>(bbox);
    k_agg2<<<N_BBOX, 128>>>(bbox, b2, out);
}

// round 6
// speedup vs baseline: 1.2998x; 1.2998x over previous
#include <cuda_runtime.h>
#include <cuda_bf16.h>
#include <cstdint>

#define N_NODES 20000
#define N_EDGES 320000
#define ET      (N_EDGES + N_NODES)   // 340000
#define GCN_IN  256
#define C1      128
#define H1      5
#define F1      (H1*C1)               // 640
#define C2      128
#define H2      3
#define F2      (H2*C2)               // 384
#define N_BBOX  4096
#define NB_SCAN ((N_NODES + 1023) / 1024)   // 20

// ---------------- scratch ---------------------------------------------------
__device__ int   g_is64;
__device__ int   g_cnt[N_NODES];
__device__ int   g_cur[N_NODES];
__device__ int   g_claim[N_NODES];
__device__ int   g_off[N_NODES + 1];
__device__ int   g_src[ET];
__device__ int   g_bsum[32];
__device__ int   g_bpre[32];
__device__ float g_xr[(size_t)N_NODES * GCN_IN];   // tf32-rounded x
__device__ float g_w1r[GCN_IN * F1];               // tf32-rounded W1
__device__ float g_w2r[F1 * F2];                   // tf32-rounded W2
__device__ float g_h1[(size_t)N_NODES * F1];
__device__ float g_o1[(size_t)N_NODES * F1];       // tf32-rounded layer1 out
__device__ float g_h2[(size_t)N_NODES * F2];
__device__ float g_as1[N_NODES * H1];
__device__ float g_ad1[N_NODES * H1];
__device__ float g_as2[N_NODES * H2];
__device__ float g_ad2[N_NODES * H2];
__device__ float g_rinv1[N_NODES * H1];
__device__ float g_rinv2[N_NODES * H2];
__device__ float g_alpha1[(size_t)ET * H1];
__device__ float g_alpha2[(size_t)ET * H2];

__device__ __forceinline__ float leaky(float x, float s) {
    return x >= 0.f ? x : s * x;
}
__device__ __forceinline__ int load_idx(const void* p, long long i) {
    return g_is64 ? (int)((const long long*)p)[i] : ((const int*)p)[i];
}
__device__ __forceinline__ uint32_t f2tf32(float x) {
    uint32_t u;
    asm("cvt.rna.tf32.f32 %0, %1;" : "=r"(u) : "f"(x));
    return u;
}

// ---------------- dtype sniff -----------------------------------------------
__global__ void k_detect(const void* ei) {
    const int* p = (const int*)ei;
    int nz = 0;
    #pragma unroll
    for (int i = 0; i < 64; i++) nz |= p[2 * i + 1];
    g_is64 = (nz == 0) ? 1 : 0;
}

// ---------------- tf32 pre-round (float4) -----------------------------------
__global__ void k_round(const float* __restrict__ in, float* __restrict__ out, int n4) {
    int i = blockIdx.x * blockDim.x + threadIdx.x;
    if (i >= n4) return;
    float4 v = reinterpret_cast<const float4*>(in)[i];
    v.x = __uint_as_float(f2tf32(v.x));
    v.y = __uint_as_float(f2tf32(v.y));
    v.z = __uint_as_float(f2tf32(v.z));
    v.w = __uint_as_float(f2tf32(v.w));
    reinterpret_cast<float4*>(out)[i] = v;
}

// ---------------- CSR build -------------------------------------------------
__global__ void k_zero() {
    int i = blockIdx.x * blockDim.x + threadIdx.x;
    if (i < N_NODES) { g_cnt[i] = 0; g_cur[i] = 0; g_claim[i] = 0; }
}

__global__ void k_hist(const void* __restrict__ ei) {
    int e = blockIdx.x * blockDim.x + threadIdx.x;
    if (e >= ET) return;
    int dst = (e < N_EDGES) ? load_idx(ei, (long long)N_EDGES + e) : (e - N_EDGES);
    atomicAdd(&g_cnt[dst], 1);
}

__global__ void k_scan1() {
    __shared__ int ws[32];
    int tid = threadIdx.x, lane = tid & 31, wid = tid >> 5;
    int i = blockIdx.x * 1024 + tid;
    int v = (i < N_NODES) ? g_cnt[i] : 0;
    int x = v;
    #pragma unroll
    for (int o = 1; o < 32; o <<= 1) {
        int y = __shfl_up_sync(~0u, x, o);
        if (lane >= o) x += y;
    }
    if (lane == 31) ws[wid] = x;
    __syncthreads();
    if (wid == 0) {
        int w = ws[lane];
        #pragma unroll
        for (int o = 1; o < 32; o <<= 1) {
            int y = __shfl_up_sync(~0u, w, o);
            if (lane >= o) w += y;
        }
        ws[lane] = w;
    }
    __syncthreads();
    int incl = x + (wid > 0 ? ws[wid - 1] : 0);
    if (i < N_NODES) g_off[i + 1] = incl;
    if (tid == 1023) g_bsum[blockIdx.x] = incl;
}

__global__ void k_scan2() {
    int lane = threadIdx.x;
    int v = (lane < NB_SCAN) ? g_bsum[lane] : 0;
    int x = v;
    #pragma unroll
    for (int o = 1; o < 32; o <<= 1) {
        int y = __shfl_up_sync(~0u, x, o);
        if (lane >= o) x += y;
    }
    g_bpre[lane] = x - v;
}

__global__ void k_scan3() {
    int i = blockIdx.x * 1024 + threadIdx.x;
    if (i == 0) g_off[0] = 0;
    if (i < N_NODES) g_off[i + 1] += g_bpre[blockIdx.x];
}

__global__ void k_scatter(const void* __restrict__ ei) {
    int e = blockIdx.x * blockDim.x + threadIdx.x;
    if (e >= ET) return;
    int src, dst;
    if (e < N_EDGES) {
        src = load_idx(ei, e);
        dst = load_idx(ei, (long long)N_EDGES + e);
    } else {
        src = dst = e - N_EDGES;
    }
    int p = g_off[dst] + atomicAdd(&g_cur[dst], 1);
    g_src[p] = src;
}

// ---------------- TF32 GEMM: cp.async double-buffer, conflict-free smem -----
// C[M,N] = A[M,K] @ B[K,N]; A,B pre-rounded to tf32 values.
// BM=128 BN=128 BK=16; 8 warps (4M x 2N), warp tile 32x64.
// As: [m][k] stride 20 (frag bank = 20*grp+sub -> conflict-free)
// Bs: [k][n] stride 136 (frag bank = 8*sub+grp -> conflict-free)
#define GBM 128
#define GBN 128
#define GBK 16
#define SA  20
#define SB  136

template<int MODE>
__global__ void __launch_bounds__(256, 2)
gemm_tf32(const float* __restrict__ dummy) {
    const int M = N_NODES;
    const int N = (MODE == 0) ? F1 : F2;
    const int K = (MODE == 0) ? GCN_IN : F1;
    const float* A = (MODE == 0) ? (const float*)g_xr : (const float*)g_o1;
    const float* B = (MODE == 0) ? (const float*)g_w1r : (const float*)g_w2r;
    float* C = (MODE == 0) ? g_h1 : g_h2;

    __shared__ float As[2][GBM * SA];
    __shared__ float Bs[2][GBK * SB];

    int tid = threadIdx.x, lane = tid & 31, warp = tid >> 5;
    int warp_m = (warp & 3) * 32;
    int warp_n = (warp >> 2) * 64;
    int rb = blockIdx.y * GBM, cb = blockIdx.x * GBN;
    int grp = lane >> 2, sub = lane & 3;

    // copy maps
    const int arow = tid >> 2;            // 0..63 (+64p)
    const int acol = (tid & 3) * 4;
    const int brow = tid >> 5;            // 0..7 (+8p)
    const int bcol = (tid & 31) * 4;

    float acc[2][8][4];
    #pragma unroll
    for (int i = 0; i < 2; i++)
        #pragma unroll
        for (int j = 0; j < 8; j++)
            #pragma unroll
            for (int q = 0; q < 4; q++) acc[i][j][q] = 0.f;

    auto copy_tile = [&](int t, int buf) {
        int k0 = t * GBK;
        #pragma unroll
        for (int p = 0; p < 2; p++) {
            int r = p * 64 + arow;
            const float* src = A + (size_t)(rb + r) * K + k0 + acol;
            uint32_t dst = (uint32_t)__cvta_generic_to_shared(&As[buf][r * SA + acol]);
            int sz = (rb + r < M) ? 16 : 0;
            asm volatile("cp.async.cg.shared.global [%0], [%1], 16, %2;\n"
                         :: "r"(dst), "l"(src), "r"(sz));
        }
        #pragma unroll
        for (int p = 0; p < 2; p++) {
            int r = p * 8 + brow;
            const float* src = B + (size_t)(k0 + r) * N + cb + bcol;
            uint32_t dst = (uint32_t)__cvta_generic_to_shared(&Bs[buf][r * SB + bcol]);
            asm volatile("cp.async.cg.shared.global [%0], [%1], 16;\n"
                         :: "r"(dst), "l"(src));
        }
        asm volatile("cp.async.commit_group;\n" ::: "memory");
    };

    const int T = K / GBK;
    copy_tile(0, 0);

    for (int t = 0; t < T; t++) {
        int buf = t & 1;
        if (t + 1 < T) {
            copy_tile(t + 1, buf ^ 1);
            asm volatile("cp.async.wait_group 1;\n" ::: "memory");
        } else {
            asm volatile("cp.async.wait_group 0;\n" ::: "memory");
        }
        __syncthreads();

        #pragma unroll
        for (int kk = 0; kk < 2; kk++) {
            int kb = kk * 8;
            uint32_t a[2][4];
            #pragma unroll
            for (int mt = 0; mt < 2; mt++) {
                int m = warp_m + mt * 16;
                a[mt][0] = __float_as_uint(As[buf][(m + grp    ) * SA + kb + sub    ]);
                a[mt][1] = __float_as_uint(As[buf][(m + grp + 8) * SA + kb + sub    ]);
                a[mt][2] = __float_as_uint(As[buf][(m + grp    ) * SA + kb + sub + 4]);
                a[mt][3] = __float_as_uint(As[buf][(m + grp + 8) * SA + kb + sub + 4]);
            }
            #pragma unroll
            for (int nt = 0; nt < 8; nt++) {
                int n = warp_n + nt * 8 + grp;
                uint32_t b0 = __float_as_uint(Bs[buf][(kb + sub    ) * SB + n]);
                uint32_t b1 = __float_as_uint(Bs[buf][(kb + sub + 4) * SB + n]);
                #pragma unroll
                for (int mt = 0; mt < 2; mt++) {
                    asm volatile(
                        "mma.sync.aligned.m16n8k8.row.col.f32.tf32.tf32.f32 "
                        "{%0,%1,%2,%3}, {%4,%5,%6,%7}, {%8,%9}, {%0,%1,%2,%3};"
                        : "+f"(acc[mt][nt][0]), "+f"(acc[mt][nt][1]),
                          "+f"(acc[mt][nt][2]), "+f"(acc[mt][nt][3])
                        : "r"(a[mt][0]), "r"(a[mt][1]), "r"(a[mt][2]), "r"(a[mt][3]),
                          "r"(b0), "r"(b1));
                }
            }
        }
        __syncthreads();
    }

    #pragma unroll
    for (int mt = 0; mt < 2; mt++) {
        int r0 = rb + warp_m + mt * 16 + grp;
        #pragma unroll
        for (int nt = 0; nt < 8; nt++) {
            int c0 = cb + warp_n + nt * 8 + 2 * sub;
            if (r0 < M)
                *reinterpret_cast<float2*>(C + (size_t)r0 * N + c0) =
                    make_float2(acc[mt][nt][0], acc[mt][nt][1]);
            if (r0 + 8 < M)
                *reinterpret_cast<float2*>(C + (size_t)(r0 + 8) * N + c0) =
                    make_float2(acc[mt][nt][2], acc[mt][nt][3]);
        }
    }
}

// ---------------- attention logits ------------------------------------------
template<int MODE>
__global__ void k_att(const float* __restrict__ asrc, const float* __restrict__ adst) {
    const int H = (MODE == 0) ? H1 : H2;
    const float* h = (MODE == 0) ? (const float*)g_h1 : (const float*)g_h2;
    float* oas = (MODE == 0) ? g_as1 : g_as2;
    float* oad = (MODE == 0) ? g_ad1 : g_ad2;
    int w = (blockIdx.x * blockDim.x + threadIdx.x) >> 5;
    int lane = threadIdx.x & 31;
    if (w >= N_NODES * H) return;
    int n = w / H, hh = w % H;
    const float* hp = h + (size_t)n * (H * 128) + hh * 128;
    const float* ap = asrc + hh * 128;
    const float* bp = adst + hh * 128;
    float s = 0.f, d = 0.f;
    #pragma unroll
    for (int j = 0; j < 4; j++) {
        float v = hp[lane + 32 * j];
        s += v * ap[lane + 32 * j];
        d += v * bp[lane + 32 * j];
    }
    #pragma unroll
    for (int o = 16; o; o >>= 1) {
        s += __shfl_xor_sync(~0u, s, o);
        d += __shfl_xor_sync(~0u, d, o);
    }
    if (lane == 0) { oas[w] = s; oad[w] = d; }
}

// ---------------- segment softmax: store exp + 1/denom ----------------------
template<int H>
__device__ __forceinline__ void softmax_node(int n, const float* as_, const float* ad_,
                                             float* alpha, float* rinvg, int lane) {
    int beg = g_off[n], end = g_off[n + 1];
    float ad[H], m[H], dsum[H];
    #pragma unroll
    for (int h = 0; h < H; h++) { ad[h] = ad_[n * H + h]; m[h] = -1e30f; dsum[h] = 0.f; }
    for (int i = beg + lane; i < end; i += 32) {
        int s = g_src[i];
        #pragma unroll
        for (int h = 0; h < H; h++) {
            float e = leaky(as_[s * H + h] + ad[h], 0.2f);
            alpha[(size_t)i * H + h] = e;
            m[h] = fmaxf(m[h], e);
        }
    }
    #pragma unroll
    for (int h = 0; h < H; h++)
        #pragma unroll
        for (int o = 16; o; o >>= 1) m[h] = fmaxf(m[h], __shfl_xor_sync(~0u, m[h], o));
    for (int i = beg + lane; i < end; i += 32) {
        #pragma unroll
        for (int h = 0; h < H; h++) {
            float ex = expf(alpha[(size_t)i * H + h] - m[h]);
            alpha[(size_t)i * H + h] = ex;
            dsum[h] += ex;
        }
    }
    #pragma unroll
    for (int h = 0; h < H; h++)
        #pragma unroll
        for (int o = 16; o; o >>= 1) dsum[h] += __shfl_xor_sync(~0u, dsum[h], o);
    if (lane == 0)
        #pragma unroll
        for (int h = 0; h < H; h++) rinvg[n * H + h] = 1.f / (dsum[h] + 1e-16f);
}

__global__ void k_softmax1() {
    int n = (blockIdx.x * blockDim.x + threadIdx.x) >> 5;
    int lane = threadIdx.x & 31;
    if (n >= N_NODES) return;
    softmax_node<H1>(n, g_as1, g_ad1, g_alpha1, g_rinv1, lane);
}

__global__ void k_softmax2(const void* __restrict__ bbox) {
    int wi = (blockIdx.x * blockDim.x + threadIdx.x) >> 5;
    int lane = threadIdx.x & 31;
    if (wi >= N_BBOX) return;
    int n = load_idx(bbox, wi);
    int claimed = 0;
    if (lane == 0) claimed = atomicExch(&g_claim[n], 1);
    claimed = __shfl_sync(~0u, claimed, 0);
    if (claimed) return;
    softmax_node<H2>(n, g_as2, g_ad2, g_alpha2, g_rinv2, lane);
}

// ---------------- layer-1 aggregation, 4x edge unroll -----------------------
__global__ void k_agg1(const float* __restrict__ b1) {
    int n = blockIdx.x;
    int t = threadIdx.x;
    int beg = g_off[n], end = g_off[n + 1];
    float acc[H1] = {0.f, 0.f, 0.f, 0.f, 0.f};
    int i = beg;
    for (; i + 4 <= end; i += 4) {
        int s0 = g_src[i], s1 = g_src[i + 1], s2 = g_src[i + 2], s3 = g_src[i + 3];
        const float* p0 = g_h1 + (size_t)s0 * F1;
        const float* p1 = g_h1 + (size_t)s1 * F1;
        const float* p2 = g_h1 + (size_t)s2 * F1;
        const float* p3 = g_h1 + (size_t)s3 * F1;
        float al[4][H1];
        #pragma unroll
        for (int e = 0; e < 4; e++)
            #pragma unroll
            for (int h = 0; h < H1; h++) al[e][h] = g_alpha1[(size_t)(i + e) * H1 + h];
        #pragma unroll
        for (int h = 0; h < H1; h++) {
            acc[h] += al[0][h] * p0[h * 128 + t];
            acc[h] += al[1][h] * p1[h * 128 + t];
            acc[h] += al[2][h] * p2[h * 128 + t];
            acc[h] += al[3][h] * p3[h * 128 + t];
        }
    }
    for (; i < end; i++) {
        int s = g_src[i];
        const float* hp = g_h1 + (size_t)s * F1;
        #pragma unroll
        for (int h = 0; h < H1; h++)
            acc[h] += g_alpha1[(size_t)i * H1 + h] * hp[h * 128 + t];
    }
    #pragma unroll
    for (int h = 0; h < H1; h++) {
        float v = acc[h] * g_rinv1[n * H1 + h] + b1[h * 128 + t];
        // tf32-round here: o1 is consumed only by gemm2
        g_o1[(size_t)n * F1 + h * 128 + t] = __uint_as_float(f2tf32(leaky(v, 0.01f)));
    }
}

// ---------------- layer-2 aggregation: bbox entries, 4x unroll --------------
__global__ void k_agg2(const void* __restrict__ bbox, const float* __restrict__ b2,
                       float* __restrict__ out) {
    int bi = blockIdx.x;
    int t = threadIdx.x;
    int n = load_idx(bbox, bi);
    int beg = g_off[n], end = g_off[n + 1];
    float acc[H2] = {0.f, 0.f, 0.f};
    int e = beg;
    for (; e + 4 <= end; e += 4) {
        int s0 = g_src[e], s1 = g_src[e + 1], s2 = g_src[e + 2], s3 = g_src[e + 3];
        const float* p0 = g_h2 + (size_t)s0 * F2;
        const float* p1 = g_h2 + (size_t)s1 * F2;
        const float* p2 = g_h2 + (size_t)s2 * F2;
        const float* p3 = g_h2 + (size_t)s3 * F2;
        float al[4][H2];
        #pragma unroll
        for (int q = 0; q < 4; q++)
            #pragma unroll
            for (int h = 0; h < H2; h++) al[q][h] = g_alpha2[(size_t)(e + q) * H2 + h];
        #pragma unroll
        for (int h = 0; h < H2; h++) {
            acc[h] += al[0][h] * p0[h * 128 + t];
            acc[h] += al[1][h] * p1[h * 128 + t];
            acc[h] += al[2][h] * p2[h * 128 + t];
            acc[h] += al[3][h] * p3[h * 128 + t];
        }
    }
    for (; e < end; e++) {
        int s = g_src[e];
        const float* hp = g_h2 + (size_t)s * F2;
        #pragma unroll
        for (int h = 0; h < H2; h++)
            acc[h] += g_alpha2[(size_t)e * H2 + h] * hp[h * 128 + t];
    }
    float v = (acc[0] * g_rinv2[n * H2 + 0] +
               acc[1] * g_rinv2[n * H2 + 1] +
               acc[2] * g_rinv2[n * H2 + 2]) * (1.f / 3.f) + b2[t];
    out[(size_t)bi * 128 + t] = leaky(v, 0.01f);
}

// ---------------- launch ----------------------------------------------------
extern "C" void kernel_launch(void* const* d_in, const int* in_sizes, int n_in,
                              void* d_out, int out_size) {
    const float *x = nullptr, *W1 = nullptr, *W2 = nullptr, *b1 = nullptr, *b2 = nullptr;
    const float *att_src1 = nullptr, *att_dst1 = nullptr;
    const float *att_src2 = nullptr, *att_dst2 = nullptr;
    const void *ei = nullptr, *bbox = nullptr;
    int n640 = 0, n384 = 0;
    for (int i = 0; i < n_in; i++) {
        switch (in_sizes[i]) {
            case N_NODES * GCN_IN: x    = (const float*)d_in[i]; break;
            case 2 * N_EDGES:      ei   = d_in[i]; break;
            case N_BBOX:           bbox = d_in[i]; break;
            case GCN_IN * F1:      W1   = (const float*)d_in[i]; break;
            case F1 * F2:          W2   = (const float*)d_in[i]; break;
            case C2:               b2   = (const float*)d_in[i]; break;
            case F1:
                if      (n640 == 0) att_src1 = (const float*)d_in[i];
                else if (n640 == 1) att_dst1 = (const float*)d_in[i];
                else                b1       = (const float*)d_in[i];
                n640++; break;
            case F2:
                if (n384 == 0) att_src2 = (const float*)d_in[i];
                else           att_dst2 = (const float*)d_in[i];
                n384++; break;
            default: break;
        }
    }
    float* out = (float*)d_out;

    float *xr, *w1r, *w2r;
    cudaGetSymbolAddress((void**)&xr,  g_xr);
    cudaGetSymbolAddress((void**)&w1r, g_w1r);
    cudaGetSymbolAddress((void**)&w2r, g_w2r);

    k_detect<<<1, 1>>>(ei);                                              // 0
    k_round<<<(N_NODES * GCN_IN / 4 + 255) / 256, 256>>>(x, xr, N_NODES * GCN_IN / 4);   // 1
    k_round<<<(GCN_IN * F1 / 4 + 255) / 256, 256>>>(W1, w1r, GCN_IN * F1 / 4);           // 2
    {                                                                    // 3 (profiled slot)
        dim3 g(F1 / GBN, (N_NODES + GBM - 1) / GBM);
        gemm_tf32<0><<<g, 256>>>(nullptr);
    }
    k_round<<<(F1 * F2 / 4 + 255) / 256, 256>>>(W2, w2r, F1 * F2 / 4);
    k_zero<<<(N_NODES + 255) / 256, 256>>>();
    k_hist<<<(ET + 255) / 256, 256>>>(ei);
    k_scan1<<<NB_SCAN, 1024>>>();
    k_scan2<<<1, 32>>>();
    k_scan3<<<NB_SCAN, 1024>>>();
    k_scatter<<<(ET + 255) / 256, 256>>>(ei);

    k_att<0><<<(N_NODES * H1 * 32 + 255) / 256, 256>>>(att_src1, att_dst1);
    k_softmax1<<<(N_NODES * 32 + 255) / 256, 256>>>();
    k_agg1<<<N_NODES, 128>>>(b1);

    {
        dim3 g(F2 / GBN, (N_NODES + GBM - 1) / GBM);
        gemm_tf32<1><<<g, 256>>>(nullptr);
    }
    k_att<1><<<(N_NODES * H2 * 32 + 255) / 256, 256>>>(att_src2, att_dst2);
    k_softmax2<<<(N_BBOX * 32 + 255) / 256, 256>>>(bbox);
    k_agg2<<<N_BBOX, 128>>>(bbox, b2, out);
}

// round 7
// speedup vs baseline: 1.5863x; 1.2204x over previous
#include <cuda_runtime.h>
#include <cuda_bf16.h>
#include <cstdint>

#define N_NODES 20000
#define N_EDGES 320000
#define ET      (N_EDGES + N_NODES)   // 340000
#define GCN_IN  256
#define C1      128
#define H1      5
#define F1      (H1*C1)               // 640
#define C2      128
#define H2      3
#define F2      (H2*C2)               // 384
#define N_BBOX  4096
#define NB_SCAN ((N_NODES + 1023) / 1024)   // 20

// ---------------- scratch ---------------------------------------------------
__device__ int   g_is64;
__device__ int   g_cnt[N_NODES];
__device__ int   g_cur[N_NODES];
__device__ int   g_claim[N_NODES];
__device__ int   g_off[N_NODES + 1];
__device__ int   g_src[ET];
__device__ int   g_bsum[32];
__device__ int   g_bpre[32];
__device__ float g_xr[(size_t)N_NODES * GCN_IN];   // tf32-rounded x
__device__ float g_w1r[GCN_IN * F1];               // tf32-rounded W1
__device__ float g_w2r[F1 * F2];                   // tf32-rounded W2
__device__ float g_h1[(size_t)N_NODES * F1];
__device__ float g_o1[(size_t)N_NODES * F1];       // tf32-rounded layer1 out
__device__ float g_h2[(size_t)N_NODES * F2];
__device__ float g_as1[N_NODES * H1];
__device__ float g_ad1[N_NODES * H1];
__device__ float g_as2[N_NODES * H2];
__device__ float g_ad2[N_NODES * H2];
__device__ float g_rinv1[N_NODES * H1];
__device__ float g_rinv2[N_NODES * H2];
__device__ float g_alpha1[(size_t)ET * H1];
__device__ float g_alpha2[(size_t)ET * H2];

__device__ __forceinline__ float leaky(float x, float s) {
    return x >= 0.f ? x : s * x;
}
__device__ __forceinline__ int load_idx(const void* p, long long i) {
    return g_is64 ? (int)((const long long*)p)[i] : ((const int*)p)[i];
}
__device__ __forceinline__ uint32_t f2tf32(float x) {
    uint32_t u;
    asm("cvt.rna.tf32.f32 %0, %1;" : "=r"(u) : "f"(x));
    return u;
}

// ---------------- dtype sniff -----------------------------------------------
__global__ void k_detect(const void* ei) {
    const int* p = (const int*)ei;
    int nz = 0;
    #pragma unroll
    for (int i = 0; i < 64; i++) nz |= p[2 * i + 1];
    g_is64 = (nz == 0) ? 1 : 0;
}

// ---------------- tf32 pre-round (float4) -----------------------------------
__global__ void k_round(const float* __restrict__ in, float* __restrict__ out, int n4) {
    int i = blockIdx.x * blockDim.x + threadIdx.x;
    if (i >= n4) return;
    float4 v = reinterpret_cast<const float4*>(in)[i];
    v.x = __uint_as_float(f2tf32(v.x));
    v.y = __uint_as_float(f2tf32(v.y));
    v.z = __uint_as_float(f2tf32(v.z));
    v.w = __uint_as_float(f2tf32(v.w));
    reinterpret_cast<float4*>(out)[i] = v;
}

// ---------------- CSR build -------------------------------------------------
__global__ void k_zero() {
    int i = blockIdx.x * blockDim.x + threadIdx.x;
    if (i < N_NODES) { g_cnt[i] = 0; g_cur[i] = 0; g_claim[i] = 0; }
}

__global__ void k_hist(const void* __restrict__ ei) {
    int e = blockIdx.x * blockDim.x + threadIdx.x;
    if (e >= ET) return;
    int dst = (e < N_EDGES) ? load_idx(ei, (long long)N_EDGES + e) : (e - N_EDGES);
    atomicAdd(&g_cnt[dst], 1);
}

__global__ void k_scan1() {
    __shared__ int ws[32];
    int tid = threadIdx.x, lane = tid & 31, wid = tid >> 5;
    int i = blockIdx.x * 1024 + tid;
    int v = (i < N_NODES) ? g_cnt[i] : 0;
    int x = v;
    #pragma unroll
    for (int o = 1; o < 32; o <<= 1) {
        int y = __shfl_up_sync(~0u, x, o);
        if (lane >= o) x += y;
    }
    if (lane == 31) ws[wid] = x;
    __syncthreads();
    if (wid == 0) {
        int w = ws[lane];
        #pragma unroll
        for (int o = 1; o < 32; o <<= 1) {
            int y = __shfl_up_sync(~0u, w, o);
            if (lane >= o) w += y;
        }
        ws[lane] = w;
    }
    __syncthreads();
    int incl = x + (wid > 0 ? ws[wid - 1] : 0);
    if (i < N_NODES) g_off[i + 1] = incl;
    if (tid == 1023) g_bsum[blockIdx.x] = incl;
}

__global__ void k_scan2() {
    int lane = threadIdx.x;
    int v = (lane < NB_SCAN) ? g_bsum[lane] : 0;
    int x = v;
    #pragma unroll
    for (int o = 1; o < 32; o <<= 1) {
        int y = __shfl_up_sync(~0u, x, o);
        if (lane >= o) x += y;
    }
    g_bpre[lane] = x - v;
}

__global__ void k_scan3() {
    int i = blockIdx.x * 1024 + threadIdx.x;
    if (i == 0) g_off[0] = 0;
    if (i < N_NODES) g_off[i + 1] += g_bpre[blockIdx.x];
}

__global__ void k_scatter(const void* __restrict__ ei) {
    int e = blockIdx.x * blockDim.x + threadIdx.x;
    if (e >= ET) return;
    int src, dst;
    if (e < N_EDGES) {
        src = load_idx(ei, e);
        dst = load_idx(ei, (long long)N_EDGES + e);
    } else {
        src = dst = e - N_EDGES;
    }
    int p = g_off[dst] + atomicAdd(&g_cur[dst], 1);
    g_src[p] = src;
}

// ---------------- TF32 GEMM: 3-stage cp.async pipeline ----------------------
// C[M,N] = A[M,K] @ B[K,N]; A,B pre-rounded tf32 values.
// BM=128 BN=128 BK=16; 8 warps (4M x 2N), warp tile 32x64. 1 sync per tile.
#define GBM 128
#define GBN 128
#define GBK 16
#define SA  20
#define SB  136
#define STG 3
#define GEMM_SMEM (STG * (GBM * SA + GBK * SB) * 4)

template<int MODE>
__global__ void __launch_bounds__(256, 2)
gemm_tf32() {
    const int M = N_NODES;
    const int N = (MODE == 0) ? F1 : F2;
    const int K = (MODE == 0) ? GCN_IN : F1;
    const float* A = (MODE == 0) ? (const float*)g_xr : (const float*)g_o1;
    const float* B = (MODE == 0) ? (const float*)g_w1r : (const float*)g_w2r;
    float* C = (MODE == 0) ? g_h1 : g_h2;

    extern __shared__ float smem[];
    float* As = smem;                       // [STG][GBM*SA]
    float* Bs = smem + STG * GBM * SA;      // [STG][GBK*SB]

    int tid = threadIdx.x, lane = tid & 31, warp = tid >> 5;
    int warp_m = (warp & 3) * 32;
    int warp_n = (warp >> 2) * 64;
    int rb = blockIdx.y * GBM, cb = blockIdx.x * GBN;
    int grp = lane >> 2, sub = lane & 3;

    const int arow = tid >> 2;            // 0..63 (+64p)
    const int acol = (tid & 3) * 4;
    const int brow = tid >> 5;            // 0..7 (+8p)
    const int bcol = (tid & 31) * 4;

    float acc[2][8][4];
    #pragma unroll
    for (int i = 0; i < 2; i++)
        #pragma unroll
        for (int j = 0; j < 8; j++)
            #pragma unroll
            for (int q = 0; q < 4; q++) acc[i][j][q] = 0.f;

    auto copy_tile = [&](int t, int buf) {
        int k0 = t * GBK;
        float* Ab = As + buf * GBM * SA;
        float* Bb = Bs + buf * GBK * SB;
        #pragma unroll
        for (int p = 0; p < 2; p++) {
            int r = p * 64 + arow;
            const float* src = A + (size_t)(rb + r) * K + k0 + acol;
            uint32_t dst = (uint32_t)__cvta_generic_to_shared(&Ab[r * SA + acol]);
            int sz = (rb + r < M) ? 16 : 0;
            asm volatile("cp.async.cg.shared.global [%0], [%1], 16, %2;\n"
                         :: "r"(dst), "l"(src), "r"(sz));
        }
        #pragma unroll
        for (int p = 0; p < 2; p++) {
            int r = p * 8 + brow;
            const float* src = B + (size_t)(k0 + r) * N + cb + bcol;
            uint32_t dst = (uint32_t)__cvta_generic_to_shared(&Bb[r * SB + bcol]);
            asm volatile("cp.async.cg.shared.global [%0], [%1], 16;\n"
                         :: "r"(dst), "l"(src));
        }
        asm volatile("cp.async.commit_group;\n" ::: "memory");
    };

    const int T = K / GBK;
    copy_tile(0, 0);
    copy_tile(1, 1);

    for (int t = 0; t < T; t++) {
        if (t < T - 1)
            asm volatile("cp.async.wait_group 1;\n" ::: "memory");
        else
            asm volatile("cp.async.wait_group 0;\n" ::: "memory");
        __syncthreads();
        if (t + 2 < T) copy_tile(t + 2, (t + 2) % STG);

        int buf = t % STG;
        const float* Ab = As + buf * GBM * SA;
        const float* Bb = Bs + buf * GBK * SB;

        #pragma unroll
        for (int kk = 0; kk < 2; kk++) {
            int kb = kk * 8;
            uint32_t a[2][4];
            #pragma unroll
            for (int mt = 0; mt < 2; mt++) {
                int m = warp_m + mt * 16;
                a[mt][0] = __float_as_uint(Ab[(m + grp    ) * SA + kb + sub    ]);
                a[mt][1] = __float_as_uint(Ab[(m + grp + 8) * SA + kb + sub    ]);
                a[mt][2] = __float_as_uint(Ab[(m + grp    ) * SA + kb + sub + 4]);
                a[mt][3] = __float_as_uint(Ab[(m + grp + 8) * SA + kb + sub + 4]);
            }
            #pragma unroll
            for (int nt = 0; nt < 8; nt++) {
                int n = warp_n + nt * 8 + grp;
                uint32_t b0 = __float_as_uint(Bb[(kb + sub    ) * SB + n]);
                uint32_t b1 = __float_as_uint(Bb[(kb + sub + 4) * SB + n]);
                #pragma unroll
                for (int mt = 0; mt < 2; mt++) {
                    asm volatile(
                        "mma.sync.aligned.m16n8k8.row.col.f32.tf32.tf32.f32 "
                        "{%0,%1,%2,%3}, {%4,%5,%6,%7}, {%8,%9}, {%0,%1,%2,%3};"
                        : "+f"(acc[mt][nt][0]), "+f"(acc[mt][nt][1]),
                          "+f"(acc[mt][nt][2]), "+f"(acc[mt][nt][3])
                        : "r"(a[mt][0]), "r"(a[mt][1]), "r"(a[mt][2]), "r"(a[mt][3]),
                          "r"(b0), "r"(b1));
                }
            }
        }
    }

    #pragma unroll
    for (int mt = 0; mt < 2; mt++) {
        int r0 = rb + warp_m + mt * 16 + grp;
        #pragma unroll
        for (int nt = 0; nt < 8; nt++) {
            int c0 = cb + warp_n + nt * 8 + 2 * sub;
            if (r0 < M)
                *reinterpret_cast<float2*>(C + (size_t)r0 * N + c0) =
                    make_float2(acc[mt][nt][0], acc[mt][nt][1]);
            if (r0 + 8 < M)
                *reinterpret_cast<float2*>(C + (size_t)(r0 + 8) * N + c0) =
                    make_float2(acc[mt][nt][2], acc[mt][nt][3]);
        }
    }
}

// ---------------- attention logits ------------------------------------------
template<int MODE>
__global__ void k_att(const float* __restrict__ asrc, const float* __restrict__ adst) {
    const int H = (MODE == 0) ? H1 : H2;
    const float* h = (MODE == 0) ? (const float*)g_h1 : (const float*)g_h2;
    float* oas = (MODE == 0) ? g_as1 : g_as2;
    float* oad = (MODE == 0) ? g_ad1 : g_ad2;
    int w = (blockIdx.x * blockDim.x + threadIdx.x) >> 5;
    int lane = threadIdx.x & 31;
    if (w >= N_NODES * H) return;
    int n = w / H, hh = w % H;
    const float* hp = h + (size_t)n * (H * 128) + hh * 128;
    const float* ap = asrc + hh * 128;
    const float* bp = adst + hh * 128;
    float s = 0.f, d = 0.f;
    #pragma unroll
    for (int j = 0; j < 4; j++) {
        float v = hp[lane + 32 * j];
        s += v * ap[lane + 32 * j];
        d += v * bp[lane + 32 * j];
    }
    #pragma unroll
    for (int o = 16; o; o >>= 1) {
        s += __shfl_xor_sync(~0u, s, o);
        d += __shfl_xor_sync(~0u, d, o);
    }
    if (lane == 0) { oas[w] = s; oad[w] = d; }
}

// ---------------- segment softmax: store exp + 1/denom ----------------------
template<int H>
__device__ __forceinline__ void softmax_node(int n, const float* as_, const float* ad_,
                                             float* alpha, float* rinvg, int lane) {
    int beg = g_off[n], end = g_off[n + 1];
    float ad[H], m[H], dsum[H];
    #pragma unroll
    for (int h = 0; h < H; h++) { ad[h] = ad_[n * H + h]; m[h] = -1e30f; dsum[h] = 0.f; }
    for (int i = beg + lane; i < end; i += 32) {
        int s = g_src[i];
        #pragma unroll
        for (int h = 0; h < H; h++) {
            float e = leaky(as_[s * H + h] + ad[h], 0.2f);
            alpha[(size_t)i * H + h] = e;
            m[h] = fmaxf(m[h], e);
        }
    }
    #pragma unroll
    for (int h = 0; h < H; h++)
        #pragma unroll
        for (int o = 16; o; o >>= 1) m[h] = fmaxf(m[h], __shfl_xor_sync(~0u, m[h], o));
    for (int i = beg + lane; i < end; i += 32) {
        #pragma unroll
        for (int h = 0; h < H; h++) {
            float ex = expf(alpha[(size_t)i * H + h] - m[h]);
            alpha[(size_t)i * H + h] = ex;
            dsum[h] += ex;
        }
    }
    #pragma unroll
    for (int h = 0; h < H; h++)
        #pragma unroll
        for (int o = 16; o; o >>= 1) dsum[h] += __shfl_xor_sync(~0u, dsum[h], o);
    if (lane == 0)
        #pragma unroll
        for (int h = 0; h < H; h++) rinvg[n * H + h] = 1.f / (dsum[h] + 1e-16f);
}

__global__ void k_softmax1() {
    int n = (blockIdx.x * blockDim.x + threadIdx.x) >> 5;
    int lane = threadIdx.x & 31;
    if (n >= N_NODES) return;
    softmax_node<H1>(n, g_as1, g_ad1, g_alpha1, g_rinv1, lane);
}

__global__ void k_softmax2(const void* __restrict__ bbox) {
    int wi = (blockIdx.x * blockDim.x + threadIdx.x) >> 5;
    int lane = threadIdx.x & 31;
    if (wi >= N_BBOX) return;
    int n = load_idx(bbox, wi);
    int claimed = 0;
    if (lane == 0) claimed = atomicExch(&g_claim[n], 1);
    claimed = __shfl_sync(~0u, claimed, 0);
    if (claimed) return;
    softmax_node<H2>(n, g_as2, g_ad2, g_alpha2, g_rinv2, lane);
}

// ---------------- layer-1 aggregation: warp-per-head, float4 ----------------
__global__ void k_agg1(const float* __restrict__ b1) {
    int n = blockIdx.x;
    int head = threadIdx.x >> 5;           // 0..4
    int lane = threadIdx.x & 31;
    int c = head * 128 + lane * 4;         // channel base
    int beg = g_off[n], end = g_off[n + 1];
    float4 acc = make_float4(0.f, 0.f, 0.f, 0.f);
    int i = beg;
    for (; i + 4 <= end; i += 4) {
        int s0 = g_src[i], s1 = g_src[i + 1], s2 = g_src[i + 2], s3 = g_src[i + 3];
        float a0 = g_alpha1[(size_t)(i    ) * H1 + head];
        float a1 = g_alpha1[(size_t)(i + 1) * H1 + head];
        float a2 = g_alpha1[(size_t)(i + 2) * H1 + head];
        float a3 = g_alpha1[(size_t)(i + 3) * H1 + head];
        float4 v0 = *reinterpret_cast<const float4*>(g_h1 + (size_t)s0 * F1 + c);
        float4 v1 = *reinterpret_cast<const float4*>(g_h1 + (size_t)s1 * F1 + c);
        float4 v2 = *reinterpret_cast<const float4*>(g_h1 + (size_t)s2 * F1 + c);
        float4 v3 = *reinterpret_cast<const float4*>(g_h1 + (size_t)s3 * F1 + c);
        acc.x += a0 * v0.x + a1 * v1.x + a2 * v2.x + a3 * v3.x;
        acc.y += a0 * v0.y + a1 * v1.y + a2 * v2.y + a3 * v3.y;
        acc.z += a0 * v0.z + a1 * v1.z + a2 * v2.z + a3 * v3.z;
        acc.w += a0 * v0.w + a1 * v1.w + a2 * v2.w + a3 * v3.w;
    }
    for (; i < end; i++) {
        int s = g_src[i];
        float a = g_alpha1[(size_t)i * H1 + head];
        float4 v = *reinterpret_cast<const float4*>(g_h1 + (size_t)s * F1 + c);
        acc.x += a * v.x; acc.y += a * v.y; acc.z += a * v.z; acc.w += a * v.w;
    }
    float rinv = g_rinv1[n * H1 + head];
    float4 bb = *reinterpret_cast<const float4*>(b1 + c);
    float4 o;
    o.x = __uint_as_float(f2tf32(leaky(acc.x * rinv + bb.x, 0.01f)));
    o.y = __uint_as_float(f2tf32(leaky(acc.y * rinv + bb.y, 0.01f)));
    o.z = __uint_as_float(f2tf32(leaky(acc.z * rinv + bb.z, 0.01f)));
    o.w = __uint_as_float(f2tf32(leaky(acc.w * rinv + bb.w, 0.01f)));
    *reinterpret_cast<float4*>(g_o1 + (size_t)n * F1 + c) = o;
}

// ---------------- layer-2 aggregation: bbox, warp-per-head, float4 ----------
__global__ void k_agg2(const void* __restrict__ bbox, const float* __restrict__ b2,
                       float* __restrict__ out) {
    __shared__ float4 red[H2][32];
    int bi = blockIdx.x;
    int head = threadIdx.x >> 5;           // 0..2
    int lane = threadIdx.x & 31;
    int c = head * 128 + lane * 4;
    int n = load_idx(bbox, bi);
    int beg = g_off[n], end = g_off[n + 1];
    float4 acc = make_float4(0.f, 0.f, 0.f, 0.f);
    int e = beg;
    for (; e + 4 <= end; e += 4) {
        int s0 = g_src[e], s1 = g_src[e + 1], s2 = g_src[e + 2], s3 = g_src[e + 3];
        float a0 = g_alpha2[(size_t)(e    ) * H2 + head];
        float a1 = g_alpha2[(size_t)(e + 1) * H2 + head];
        float a2 = g_alpha2[(size_t)(e + 2) * H2 + head];
        float a3 = g_alpha2[(size_t)(e + 3) * H2 + head];
        float4 v0 = *reinterpret_cast<const float4*>(g_h2 + (size_t)s0 * F2 + c);
        float4 v1 = *reinterpret_cast<const float4*>(g_h2 + (size_t)s1 * F2 + c);
        float4 v2 = *reinterpret_cast<const float4*>(g_h2 + (size_t)s2 * F2 + c);
        float4 v3 = *reinterpret_cast<const float4*>(g_h2 + (size_t)s3 * F2 + c);
        acc.x += a0 * v0.x + a1 * v1.x + a2 * v2.x + a3 * v3.x;
        acc.y += a0 * v0.y + a1 * v1.y + a2 * v2.y + a3 * v3.y;
        acc.z += a0 * v0.z + a1 * v1.z + a2 * v2.z + a3 * v3.z;
        acc.w += a0 * v0.w + a1 * v1.w + a2 * v2.w + a3 * v3.w;
    }
    for (; e < end; e++) {
        int s = g_src[e];
        float a = g_alpha2[(size_t)e * H2 + head];
        float4 v = *reinterpret_cast<const float4*>(g_h2 + (size_t)s * F2 + c);
        acc.x += a * v.x; acc.y += a * v.y; acc.z += a * v.z; acc.w += a * v.w;
    }
    float rinv = g_rinv2[n * H2 + head];
    acc.x *= rinv; acc.y *= rinv; acc.z *= rinv; acc.w *= rinv;
    red[head][lane] = acc;
    __syncthreads();
    if (head == 0) {
        float4 r0 = red[0][lane], r1 = red[1][lane], r2 = red[2][lane];
        float4 bb = *reinterpret_cast<const float4*>(b2 + lane * 4);
        float4 o;
        o.x = leaky((r0.x + r1.x + r2.x) * (1.f / 3.f) + bb.x, 0.01f);
        o.y = leaky((r0.y + r1.y + r2.y) * (1.f / 3.f) + bb.y, 0.01f);
        o.z = leaky((r0.z + r1.z + r2.z) * (1.f / 3.f) + bb.z, 0.01f);
        o.w = leaky((r0.w + r1.w + r2.w) * (1.f / 3.f) + bb.w, 0.01f);
        *reinterpret_cast<float4*>(out + (size_t)bi * 128 + lane * 4) = o;
    }
}

// ---------------- launch ----------------------------------------------------
extern "C" void kernel_launch(void* const* d_in, const int* in_sizes, int n_in,
                              void* d_out, int out_size) {
    const float *x = nullptr, *W1 = nullptr, *W2 = nullptr, *b1 = nullptr, *b2 = nullptr;
    const float *att_src1 = nullptr, *att_dst1 = nullptr;
    const float *att_src2 = nullptr, *att_dst2 = nullptr;
    const void *ei = nullptr, *bbox = nullptr;
    int n640 = 0, n384 = 0;
    for (int i = 0; i < n_in; i++) {
        switch (in_sizes[i]) {
            case N_NODES * GCN_IN: x    = (const float*)d_in[i]; break;
            case 2 * N_EDGES:      ei   = d_in[i]; break;
            case N_BBOX:           bbox = d_in[i]; break;
            case GCN_IN * F1:      W1   = (const float*)d_in[i]; break;
            case F1 * F2:          W2   = (const float*)d_in[i]; break;
            case C2:               b2   = (const float*)d_in[i]; break;
            case F1:
                if      (n640 == 0) att_src1 = (const float*)d_in[i];
                else if (n640 == 1) att_dst1 = (const float*)d_in[i];
                else                b1       = (const float*)d_in[i];
                n640++; break;
            case F2:
                if (n384 == 0) att_src2 = (const float*)d_in[i];
                else           att_dst2 = (const float*)d_in[i];
                n384++; break;
            default: break;
        }
    }
    float* out = (float*)d_out;

    float *xr, *w1r, *w2r;
    cudaGetSymbolAddress((void**)&xr,  g_xr);
    cudaGetSymbolAddress((void**)&w1r, g_w1r);
    cudaGetSymbolAddress((void**)&w2r, g_w2r);

    cudaFuncSetAttribute(gemm_tf32<0>, cudaFuncAttributeMaxDynamicSharedMemorySize, GEMM_SMEM);
    cudaFuncSetAttribute(gemm_tf32<1>, cudaFuncAttributeMaxDynamicSharedMemorySize, GEMM_SMEM);

    k_detect<<<1, 1>>>(ei);
    k_round<<<(N_NODES * GCN_IN / 4 + 255) / 256, 256>>>(x, xr, N_NODES * GCN_IN / 4);
    k_round<<<(GCN_IN * F1 / 4 + 255) / 256, 256>>>(W1, w1r, GCN_IN * F1 / 4);
    {   // profiled slot
        dim3 g(F1 / GBN, (N_NODES + GBM - 1) / GBM);
        gemm_tf32<0><<<g, 256, GEMM_SMEM>>>();
    }
    k_round<<<(F1 * F2 / 4 + 255) / 256, 256>>>(W2, w2r, F1 * F2 / 4);
    k_zero<<<(N_NODES + 255) / 256, 256>>>();
    k_hist<<<(ET + 255) / 256, 256>>>(ei);
    k_scan1<<<NB_SCAN, 1024>>>();
    k_scan2<<<1, 32>>>();
    k_scan3<<<NB_SCAN, 1024>>>();
    k_scatter<<<(ET + 255) / 256, 256>>>(ei);

    k_att<0><<<(N_NODES * H1 * 32 + 255) / 256, 256>>>(att_src1, att_dst1);
    k_softmax1<<<(N_NODES * 32 + 255) / 256, 256>>>();
    k_agg1<<<N_NODES, H1 * 32>>>(b1);

    {
        dim3 g(F2 / GBN, (N_NODES + GBM - 1) / GBM);
        gemm_tf32<1><<<g, 256, GEMM_SMEM>>>();
    }
    k_att<1><<<(N_NODES * H2 * 32 + 255) / 256, 256>>>(att_src2, att_dst2);
    k_softmax2<<<(N_BBOX * 32 + 255) / 256, 256>>>(bbox);
    k_agg2<<<N_BBOX, H2 * 32>>>(bbox, b2, out);
}

// round 8
// speedup vs baseline: 1.6191x; 1.0207x over previous
#include <cuda_runtime.h>
#include <cuda_bf16.h>
#include <cstdint>

#define N_NODES 20000
#define N_EDGES 320000
#define ET      (N_EDGES + N_NODES)   // 340000
#define GCN_IN  256
#define C1      128
#define H1      5
#define F1      (H1*C1)               // 640
#define C2      128
#define H2      3
#define F2      (H2*C2)               // 384
#define N_BBOX  4096
#define NB_SCAN ((N_NODES + 1023) / 1024)   // 20

// ---------------- scratch ---------------------------------------------------
__device__ int   g_is64;
__device__ int   g_cnt[N_NODES];
__device__ int   g_cur[N_NODES];
__device__ int   g_claim[N_NODES];
__device__ int   g_off[N_NODES + 1];
__device__ int   g_src[ET];
__device__ int   g_bsum[32];
__device__ int   g_bpre[32];
__device__ float g_xr[(size_t)N_NODES * GCN_IN];   // tf32-rounded x
__device__ float g_w1t[F1 * GCN_IN];               // W1^T, tf32-rounded [F1][256]
__device__ float g_w2t[F2 * F1];                   // W2^T, tf32-rounded [F2][640]
__device__ float g_h1[(size_t)N_NODES * F1];
__device__ float g_o1[(size_t)N_NODES * F1];       // tf32-rounded layer1 out
__device__ float g_h2[(size_t)N_NODES * F2];
__device__ float g_as1[N_NODES * H1];
__device__ float g_ad1[N_NODES * H1];
__device__ float g_as2[N_NODES * H2];
__device__ float g_ad2[N_NODES * H2];
__device__ float g_rinv1[N_NODES * H1];
__device__ float g_rinv2[N_NODES * H2];
__device__ float g_alpha1[(size_t)ET * H1];
__device__ float g_alpha2[(size_t)ET * H2];

__device__ __forceinline__ float leaky(float x, float s) {
    return x >= 0.f ? x : s * x;
}
__device__ __forceinline__ int load_idx(const void* p, long long i) {
    return g_is64 ? (int)((const long long*)p)[i] : ((const int*)p)[i];
}
__device__ __forceinline__ uint32_t f2tf32(float x) {
    uint32_t u;
    asm("cvt.rna.tf32.f32 %0, %1;" : "=r"(u) : "f"(x));
    return u;
}
__device__ __forceinline__ void ldm_x4(uint32_t (&r)[4], uint32_t addr) {
    asm volatile("ldmatrix.sync.aligned.m8n8.x4.shared.b16 {%0,%1,%2,%3}, [%4];"
                 : "=r"(r[0]), "=r"(r[1]), "=r"(r[2]), "=r"(r[3]) : "r"(addr));
}

// ---------------- dtype sniff -----------------------------------------------
__global__ void k_detect(const void* ei) {
    const int* p = (const int*)ei;
    int nz = 0;
    #pragma unroll
    for (int i = 0; i < 64; i++) nz |= p[2 * i + 1];
    g_is64 = (nz == 0) ? 1 : 0;
}

// ---------------- tf32 pre-round (float4) -----------------------------------
__global__ void k_round(const float* __restrict__ in, float* __restrict__ out, int n4) {
    int i = blockIdx.x * blockDim.x + threadIdx.x;
    if (i >= n4) return;
    float4 v = reinterpret_cast<const float4*>(in)[i];
    v.x = __uint_as_float(f2tf32(v.x));
    v.y = __uint_as_float(f2tf32(v.y));
    v.z = __uint_as_float(f2tf32(v.z));
    v.w = __uint_as_float(f2tf32(v.w));
    reinterpret_cast<float4*>(out)[i] = v;
}

// ---------------- transpose + round: W[K][N] -> Wt[N][K] --------------------
__global__ void k_transpose(const float* __restrict__ in, float* __restrict__ out,
                            int K, int N) {
    __shared__ float tile[32][33];
    int n0 = blockIdx.x * 32, k0 = blockIdx.y * 32;
    int tx = threadIdx.x, ty = threadIdx.y;
    #pragma unroll
    for (int j = 0; j < 32; j += 8)
        tile[ty + j][tx] = in[(size_t)(k0 + ty + j) * N + n0 + tx];
    __syncthreads();
    #pragma unroll
    for (int j = 0; j < 32; j += 8)
        out[(size_t)(n0 + ty + j) * K + k0 + tx] =
            __uint_as_float(f2tf32(tile[tx][ty + j]));
}

// ---------------- CSR build -------------------------------------------------
__global__ void k_zero() {
    int i = blockIdx.x * blockDim.x + threadIdx.x;
    if (i < N_NODES) { g_cnt[i] = 0; g_cur[i] = 0; g_claim[i] = 0; }
}

__global__ void k_hist(const void* __restrict__ ei) {
    int e = blockIdx.x * blockDim.x + threadIdx.x;
    if (e >= ET) return;
    int dst = (e < N_EDGES) ? load_idx(ei, (long long)N_EDGES + e) : (e - N_EDGES);
    atomicAdd(&g_cnt[dst], 1);
}

__global__ void k_scan1() {
    __shared__ int ws[32];
    int tid = threadIdx.x, lane = tid & 31, wid = tid >> 5;
    int i = blockIdx.x * 1024 + tid;
    int v = (i < N_NODES) ? g_cnt[i] : 0;
    int x = v;
    #pragma unroll
    for (int o = 1; o < 32; o <<= 1) {
        int y = __shfl_up_sync(~0u, x, o);
        if (lane >= o) x += y;
    }
    if (lane == 31) ws[wid] = x;
    __syncthreads();
    if (wid == 0) {
        int w = ws[lane];
        #pragma unroll
        for (int o = 1; o < 32; o <<= 1) {
            int y = __shfl_up_sync(~0u, w, o);
            if (lane >= o) w += y;
        }
        ws[lane] = w;
    }
    __syncthreads();
    int incl = x + (wid > 0 ? ws[wid - 1] : 0);
    if (i < N_NODES) g_off[i + 1] = incl;
    if (tid == 1023) g_bsum[blockIdx.x] = incl;
}

__global__ void k_scan2() {
    int lane = threadIdx.x;
    int v = (lane < NB_SCAN) ? g_bsum[lane] : 0;
    int x = v;
    #pragma unroll
    for (int o = 1; o < 32; o <<= 1) {
        int y = __shfl_up_sync(~0u, x, o);
        if (lane >= o) x += y;
    }
    g_bpre[lane] = x - v;
}

__global__ void k_scan3() {
    int i = blockIdx.x * 1024 + threadIdx.x;
    if (i == 0) g_off[0] = 0;
    if (i < N_NODES) g_off[i + 1] += g_bpre[blockIdx.x];
}

__global__ void k_scatter(const void* __restrict__ ei) {
    int e = blockIdx.x * blockDim.x + threadIdx.x;
    if (e >= ET) return;
    int src, dst;
    if (e < N_EDGES) {
        src = load_idx(ei, e);
        dst = load_idx(ei, (long long)N_EDGES + e);
    } else {
        src = dst = e - N_EDGES;
    }
    int p = g_off[dst] + atomicAdd(&g_cur[dst], 1);
    g_src[p] = src;
}

// ---------------- TF32 GEMM: ldmatrix fragments + fused attention dots ------
// C[M,N] = A[M,K] @ Bt[N,K]^T. GBN=128 = one head per CTA (blockIdx.x = head).
// BM=128 BN=128 BK=16; 8 warps (4M x 2N), warp tile 32x64. 3-stage cp.async.
#define GBM 128
#define GBN 128
#define GBK 16
#define SA  20
#define SBK 20
#define STG 3
#define GEMM_SMEM (STG * (GBM * SA + GBN * SBK) * 4)

template<int MODE>
__global__ void __launch_bounds__(256, 2)
gemm_tf32(const float* __restrict__ asrc, const float* __restrict__ adst) {
    const int M = N_NODES;
    const int K = (MODE == 0) ? GCN_IN : F1;
    const int N = (MODE == 0) ? F1 : F2;
    const int H = (MODE == 0) ? H1 : H2;
    const float* A  = (MODE == 0) ? (const float*)g_xr  : (const float*)g_o1;
    const float* Bt = (MODE == 0) ? (const float*)g_w1t : (const float*)g_w2t;
    float* C   = (MODE == 0) ? g_h1  : g_h2;
    float* oas = (MODE == 0) ? g_as1 : g_as2;
    float* oad = (MODE == 0) ? g_ad1 : g_ad2;

    extern __shared__ float smem[];
    float* As = smem;                        // [STG][GBM*SA]
    float* Bs = smem + STG * GBM * SA;       // [STG][GBN*SBK]
    __shared__ float red_s[GBM], red_d[GBM];

    int tid = threadIdx.x, lane = tid & 31, warp = tid >> 5;
    int warp_m = (warp & 3) * 32;
    int warp_n = (warp >> 2) * 64;
    int head = blockIdx.x;
    int rb = blockIdx.y * GBM, cb = head * GBN;
    int grp = lane >> 2, sub = lane & 3;

    const int arow = tid >> 2;            // 0..63 (+64p)
    const int acol = (tid & 3) * 4;
    const int brow = tid >> 2;
    const int bcol = (tid & 3) * 4;

    uint32_t sAb = (uint32_t)__cvta_generic_to_shared(As);
    uint32_t sBb = (uint32_t)__cvta_generic_to_shared(Bs);
    // ldmatrix address bases (lane-encoded row + k-half)
    uint32_t aoff = sAb + (((lane & 15) + warp_m) * SA + ((lane >> 4) << 2)) * 4;
    uint32_t boff = sBb + (((lane & 15) + warp_n) * SBK + ((lane >> 4) << 2)) * 4;

    float acc[2][8][4];
    #pragma unroll
    for (int i = 0; i < 2; i++)
        #pragma unroll
        for (int j = 0; j < 8; j++)
            #pragma unroll
            for (int q = 0; q < 4; q++) acc[i][j][q] = 0.f;

    auto copy_tile = [&](int t, int buf) {
        int k0 = t * GBK;
        float* Ab = As + buf * GBM * SA;
        float* Bb = Bs + buf * GBN * SBK;
        #pragma unroll
        for (int p = 0; p < 2; p++) {
            int r = p * 64 + arow;
            const float* src = A + (size_t)(rb + r) * K + k0 + acol;
            uint32_t dst = (uint32_t)__cvta_generic_to_shared(&Ab[r * SA + acol]);
            int sz = (rb + r < M) ? 16 : 0;
            asm volatile("cp.async.cg.shared.global [%0], [%1], 16, %2;\n"
                         :: "r"(dst), "l"(src), "r"(sz));
        }
        #pragma unroll
        for (int p = 0; p < 2; p++) {
            int r = p * 64 + brow;
            const float* src = Bt + (size_t)(cb + r) * K + k0 + bcol;
            uint32_t dst = (uint32_t)__cvta_generic_to_shared(&Bb[r * SBK + bcol]);
            asm volatile("cp.async.cg.shared.global [%0], [%1], 16;\n"
                         :: "r"(dst), "l"(src));
        }
        asm volatile("cp.async.commit_group;\n" ::: "memory");
    };

    const int T = K / GBK;
    copy_tile(0, 0);
    copy_tile(1, 1);

    for (int t = 0; t < T; t++) {
        if (t < T - 1)
            asm volatile("cp.async.wait_group 1;\n" ::: "memory");
        else
            asm volatile("cp.async.wait_group 0;\n" ::: "memory");
        __syncthreads();
        if (t + 2 < T) copy_tile(t + 2, (t + 2) % STG);

        int buf = t % STG;
        uint32_t aB = aoff + buf * (GBM * SA * 4);
        uint32_t bB = boff + buf * (GBN * SBK * 4);

        #pragma unroll
        for (int kk = 0; kk < 2; kk++) {
            uint32_t a0[4], a1[4];
            ldm_x4(a0, aB + kk * 32);
            ldm_x4(a1, aB + kk * 32 + 16 * SA * 4);
            #pragma unroll
            for (int nt2 = 0; nt2 < 4; nt2++) {
                uint32_t b[4];
                ldm_x4(b, bB + kk * 32 + nt2 * (16 * SBK * 4));
                #pragma unroll
                for (int mt = 0; mt < 2; mt++) {
                    const uint32_t* a = (mt == 0) ? a0 : a1;
                    asm volatile(
                        "mma.sync.aligned.m16n8k8.row.col.f32.tf32.tf32.f32 "
                        "{%0,%1,%2,%3}, {%4,%5,%6,%7}, {%8,%9}, {%0,%1,%2,%3};"
                        : "+f"(acc[mt][2 * nt2][0]), "+f"(acc[mt][2 * nt2][1]),
                          "+f"(acc[mt][2 * nt2][2]), "+f"(acc[mt][2 * nt2][3])
                        : "r"(a[0]), "r"(a[1]), "r"(a[2]), "r"(a[3]),
                          "r"(b[0]), "r"(b[2]));
                    asm volatile(
                        "mma.sync.aligned.m16n8k8.row.col.f32.tf32.tf32.f32 "
                        "{%0,%1,%2,%3}, {%4,%5,%6,%7}, {%8,%9}, {%0,%1,%2,%3};"
                        : "+f"(acc[mt][2 * nt2 + 1][0]), "+f"(acc[mt][2 * nt2 + 1][1]),
                          "+f"(acc[mt][2 * nt2 + 1][2]), "+f"(acc[mt][2 * nt2 + 1][3])
                        : "r"(a[0]), "r"(a[1]), "r"(a[2]), "r"(a[3]),
                          "r"(b[1]), "r"(b[3]));
                }
            }
        }
    }

    // ---- store C ----
    #pragma unroll
    for (int mt = 0; mt < 2; mt++) {
        int r0 = rb + warp_m + mt * 16 + grp;
        #pragma unroll
        for (int nt = 0; nt < 8; nt++) {
            int c0 = cb + warp_n + nt * 8 + 2 * sub;
            if (r0 < M)
                *reinterpret_cast<float2*>(C + (size_t)r0 * N + c0) =
                    make_float2(acc[mt][nt][0], acc[mt][nt][1]);
            if (r0 + 8 < M)
                *reinterpret_cast<float2*>(C + (size_t)(r0 + 8) * N + c0) =
                    make_float2(acc[mt][nt][2], acc[mt][nt][3]);
        }
    }

    // ---- fused attention dots: a_s/a_d for this head ----
    float ps[2][2] = {{0.f, 0.f}, {0.f, 0.f}};
    float pd[2][2] = {{0.f, 0.f}, {0.f, 0.f}};
    #pragma unroll
    for (int nt = 0; nt < 8; nt++) {
        int cc = warp_n + nt * 8 + 2 * sub;
        float s0 = asrc[head * 128 + cc],     d0 = adst[head * 128 + cc];
        float s1 = asrc[head * 128 + cc + 1], d1 = adst[head * 128 + cc + 1];
        #pragma unroll
        for (int mt = 0; mt < 2; mt++) {
            ps[mt][0] += acc[mt][nt][0] * s0 + acc[mt][nt][1] * s1;
            pd[mt][0] += acc[mt][nt][0] * d0 + acc[mt][nt][1] * d1;
            ps[mt][1] += acc[mt][nt][2] * s0 + acc[mt][nt][3] * s1;
            pd[mt][1] += acc[mt][nt][2] * d0 + acc[mt][nt][3] * d1;
        }
    }
    #pragma unroll
    for (int mt = 0; mt < 2; mt++)
        #pragma unroll
        for (int hf = 0; hf < 2; hf++) {
            #pragma unroll
            for (int o = 1; o < 4; o <<= 1) {
                ps[mt][hf] += __shfl_xor_sync(~0u, ps[mt][hf], o);
                pd[mt][hf] += __shfl_xor_sync(~0u, pd[mt][hf], o);
            }
        }
    if (warp >= 4 && sub == 0) {
        #pragma unroll
        for (int mt = 0; mt < 2; mt++)
            #pragma unroll
            for (int hf = 0; hf < 2; hf++) {
                int lr = warp_m + mt * 16 + hf * 8 + grp;
                red_s[lr] = ps[mt][hf];
                red_d[lr] = pd[mt][hf];
            }
    }
    __syncthreads();
    if (warp < 4 && sub == 0) {
        #pragma unroll
        for (int mt = 0; mt < 2; mt++)
            #pragma unroll
            for (int hf = 0; hf < 2; hf++) {
                int lr = warp_m + mt * 16 + hf * 8 + grp;
                int r = rb + lr;
                if (r < M) {
                    oas[r * H + head] = ps[mt][hf] + red_s[lr];
                    oad[r * H + head] = pd[mt][hf] + red_d[lr];
                }
            }
    }
}

// ---------------- segment softmax: store exp + 1/denom ----------------------
template<int H>
__device__ __forceinline__ void softmax_node(int n, const float* as_, const float* ad_,
                                             float* alpha, float* rinvg, int lane) {
    int beg = g_off[n], end = g_off[n + 1];
    float ad[H], m[H], dsum[H];
    #pragma unroll
    for (int h = 0; h < H; h++) { ad[h] = ad_[n * H + h]; m[h] = -1e30f; dsum[h] = 0.f; }
    for (int i = beg + lane; i < end; i += 32) {
        int s = g_src[i];
        #pragma unroll
        for (int h = 0; h < H; h++) {
            float e = leaky(as_[s * H + h] + ad[h], 0.2f);
            alpha[(size_t)i * H + h] = e;
            m[h] = fmaxf(m[h], e);
        }
    }
    #pragma unroll
    for (int h = 0; h < H; h++)
        #pragma unroll
        for (int o = 16; o; o >>= 1) m[h] = fmaxf(m[h], __shfl_xor_sync(~0u, m[h], o));
    for (int i = beg + lane; i < end; i += 32) {
        #pragma unroll
        for (int h = 0; h < H; h++) {
            float ex = expf(alpha[(size_t)i * H + h] - m[h]);
            alpha[(size_t)i * H + h] = ex;
            dsum[h] += ex;
        }
    }
    #pragma unroll
    for (int h = 0; h < H; h++)
        #pragma unroll
        for (int o = 16; o; o >>= 1) dsum[h] += __shfl_xor_sync(~0u, dsum[h], o);
    if (lane == 0)
        #pragma unroll
        for (int h = 0; h < H; h++) rinvg[n * H + h] = 1.f / (dsum[h] + 1e-16f);
}

__global__ void k_softmax1() {
    int n = (blockIdx.x * blockDim.x + threadIdx.x) >> 5;
    int lane = threadIdx.x & 31;
    if (n >= N_NODES) return;
    softmax_node<H1>(n, g_as1, g_ad1, g_alpha1, g_rinv1, lane);
}

__global__ void k_softmax2(const void* __restrict__ bbox) {
    int wi = (blockIdx.x * blockDim.x + threadIdx.x) >> 5;
    int lane = threadIdx.x & 31;
    if (wi >= N_BBOX) return;
    int n = load_idx(bbox, wi);
    int claimed = 0;
    if (lane == 0) claimed = atomicExch(&g_claim[n], 1);
    claimed = __shfl_sync(~0u, claimed, 0);
    if (claimed) return;
    softmax_node<H2>(n, g_as2, g_ad2, g_alpha2, g_rinv2, lane);
}

// ---------------- layer-1 aggregation: warp-per-head, float4 ----------------
__global__ void k_agg1(const float* __restrict__ b1) {
    int n = blockIdx.x;
    int head = threadIdx.x >> 5;           // 0..4
    int lane = threadIdx.x & 31;
    int c = head * 128 + lane * 4;
    int beg = g_off[n], end = g_off[n + 1];
    float4 acc = make_float4(0.f, 0.f, 0.f, 0.f);
    int i = beg;
    for (; i + 4 <= end; i += 4) {
        int s0 = g_src[i], s1 = g_src[i + 1], s2 = g_src[i + 2], s3 = g_src[i + 3];
        float a0 = g_alpha1[(size_t)(i    ) * H1 + head];
        float a1 = g_alpha1[(size_t)(i + 1) * H1 + head];
        float a2 = g_alpha1[(size_t)(i + 2) * H1 + head];
        float a3 = g_alpha1[(size_t)(i + 3) * H1 + head];
        float4 v0 = *reinterpret_cast<const float4*>(g_h1 + (size_t)s0 * F1 + c);
        float4 v1 = *reinterpret_cast<const float4*>(g_h1 + (size_t)s1 * F1 + c);
        float4 v2 = *reinterpret_cast<const float4*>(g_h1 + (size_t)s2 * F1 + c);
        float4 v3 = *reinterpret_cast<const float4*>(g_h1 + (size_t)s3 * F1 + c);
        acc.x += a0 * v0.x + a1 * v1.x + a2 * v2.x + a3 * v3.x;
        acc.y += a0 * v0.y + a1 * v1.y + a2 * v2.y + a3 * v3.y;
        acc.z += a0 * v0.z + a1 * v1.z + a2 * v2.z + a3 * v3.z;
        acc.w += a0 * v0.w + a1 * v1.w + a2 * v2.w + a3 * v3.w;
    }
    for (; i < end; i++) {
        int s = g_src[i];
        float a = g_alpha1[(size_t)i * H1 + head];
        float4 v = *reinterpret_cast<const float4*>(g_h1 + (size_t)s * F1 + c);
        acc.x += a * v.x; acc.y += a * v.y; acc.z += a * v.z; acc.w += a * v.w;
    }
    float rinv = g_rinv1[n * H1 + head];
    float4 bb = *reinterpret_cast<const float4*>(b1 + c);
    float4 o;
    o.x = __uint_as_float(f2tf32(leaky(acc.x * rinv + bb.x, 0.01f)));
    o.y = __uint_as_float(f2tf32(leaky(acc.y * rinv + bb.y, 0.01f)));
    o.z = __uint_as_float(f2tf32(leaky(acc.z * rinv + bb.z, 0.01f)));
    o.w = __uint_as_float(f2tf32(leaky(acc.w * rinv + bb.w, 0.01f)));
    *reinterpret_cast<float4*>(g_o1 + (size_t)n * F1 + c) = o;
}

// ---------------- layer-2 aggregation: bbox, warp-per-head, float4 ----------
__global__ void k_agg2(const void* __restrict__ bbox, const float* __restrict__ b2,
                       float* __restrict__ out) {
    __shared__ float4 red[H2][32];
    int bi = blockIdx.x;
    int head = threadIdx.x >> 5;           // 0..2
    int lane = threadIdx.x & 31;
    int c = head * 128 + lane * 4;
    int n = load_idx(bbox, bi);
    int beg = g_off[n], end = g_off[n + 1];
    float4 acc = make_float4(0.f, 0.f, 0.f, 0.f);
    int e = beg;
    for (; e + 4 <= end; e += 4) {
        int s0 = g_src[e], s1 = g_src[e + 1], s2 = g_src[e + 2], s3 = g_src[e + 3];
        float a0 = g_alpha2[(size_t)(e    ) * H2 + head];
        float a1 = g_alpha2[(size_t)(e + 1) * H2 + head];
        float a2 = g_alpha2[(size_t)(e + 2) * H2 + head];
        float a3 = g_alpha2[(size_t)(e + 3) * H2 + head];
        float4 v0 = *reinterpret_cast<const float4*>(g_h2 + (size_t)s0 * F2 + c);
        float4 v1 = *reinterpret_cast<const float4*>(g_h2 + (size_t)s1 * F2 + c);
        float4 v2 = *reinterpret_cast<const float4*>(g_h2 + (size_t)s2 * F2 + c);
        float4 v3 = *reinterpret_cast<const float4*>(g_h2 + (size_t)s3 * F2 + c);
        acc.x += a0 * v0.x + a1 * v1.x + a2 * v2.x + a3 * v3.x;
        acc.y += a0 * v0.y + a1 * v1.y + a2 * v2.y + a3 * v3.y;
        acc.z += a0 * v0.z + a1 * v1.z + a2 * v2.z + a3 * v3.z;
        acc.w += a0 * v0.w + a1 * v1.w + a2 * v2.w + a3 * v3.w;
    }
    for (; e < end; e++) {
        int s = g_src[e];
        float a = g_alpha2[(size_t)e * H2 + head];
        float4 v = *reinterpret_cast<const float4*>(g_h2 + (size_t)s * F2 + c);
        acc.x += a * v.x; acc.y += a * v.y; acc.z += a * v.z; acc.w += a * v.w;
    }
    float rinv = g_rinv2[n * H2 + head];
    acc.x *= rinv; acc.y *= rinv; acc.z *= rinv; acc.w *= rinv;
    red[head][lane] = acc;
    __syncthreads();
    if (head == 0) {
        float4 r0 = red[0][lane], r1 = red[1][lane], r2 = red[2][lane];
        float4 bb = *reinterpret_cast<const float4*>(b2 + lane * 4);
        float4 o;
        o.x = leaky((r0.x + r1.x + r2.x) * (1.f / 3.f) + bb.x, 0.01f);
        o.y = leaky((r0.y + r1.y + r2.y) * (1.f / 3.f) + bb.y, 0.01f);
        o.z = leaky((r0.z + r1.z + r2.z) * (1.f / 3.f) + bb.z, 0.01f);
        o.w = leaky((r0.w + r1.w + r2.w) * (1.f / 3.f) + bb.w, 0.01f);
        *reinterpret_cast<float4*>(out + (size_t)bi * 128 + lane * 4) = o;
    }
}

// ---------------- launch ----------------------------------------------------
extern "C" void kernel_launch(void* const* d_in, const int* in_sizes, int n_in,
                              void* d_out, int out_size) {
    const float *x = nullptr, *W1 = nullptr, *W2 = nullptr, *b1 = nullptr, *b2 = nullptr;
    const float *att_src1 = nullptr, *att_dst1 = nullptr;
    const float *att_src2 = nullptr, *att_dst2 = nullptr;
    const void *ei = nullptr, *bbox = nullptr;
    int n640 = 0, n384 = 0;
    for (int i = 0; i < n_in; i++) {
        switch (in_sizes[i]) {
            case N_NODES * GCN_IN: x    = (const float*)d_in[i]; break;
            case 2 * N_EDGES:      ei   = d_in[i]; break;
            case N_BBOX:           bbox = d_in[i]; break;
            case GCN_IN * F1:      W1   = (const float*)d_in[i]; break;
            case F1 * F2:          W2   = (const float*)d_in[i]; break;
            case C2:               b2   = (const float*)d_in[i]; break;
            case F1:
                if      (n640 == 0) att_src1 = (const float*)d_in[i];
                else if (n640 == 1) att_dst1 = (const float*)d_in[i];
                else                b1       = (const float*)d_in[i];
                n640++; break;
            case F2:
                if (n384 == 0) att_src2 = (const float*)d_in[i];
                else           att_dst2 = (const float*)d_in[i];
                n384++; break;
            default: break;
        }
    }
    float* out = (float*)d_out;

    float *xr, *w1t, *w2t;
    cudaGetSymbolAddress((void**)&xr,  g_xr);
    cudaGetSymbolAddress((void**)&w1t, g_w1t);
    cudaGetSymbolAddress((void**)&w2t, g_w2t);

    cudaFuncSetAttribute(gemm_tf32<0>, cudaFuncAttributeMaxDynamicSharedMemorySize, GEMM_SMEM);
    cudaFuncSetAttribute(gemm_tf32<1>, cudaFuncAttributeMaxDynamicSharedMemorySize, GEMM_SMEM);

    k_detect<<<1, 1>>>(ei);
    k_round<<<(N_NODES * GCN_IN / 4 + 255) / 256, 256>>>(x, xr, N_NODES * GCN_IN / 4);
    k_transpose<<<dim3(F1 / 32, GCN_IN / 32), dim3(32, 8)>>>(W1, w1t, GCN_IN, F1);
    {   // profiled slot
        dim3 g(F1 / GBN, (N_NODES + GBM - 1) / GBM);
        gemm_tf32<0><<<g, 256, GEMM_SMEM>>>(att_src1, att_dst1);
    }
    k_transpose<<<dim3(F2 / 32, F1 / 32), dim3(32, 8)>>>(W2, w2t, F1, F2);
    k_zero<<<(N_NODES + 255) / 256, 256>>>();
    k_hist<<<(ET + 255) / 256, 256>>>(ei);
    k_scan1<<<NB_SCAN, 1024>>>();
    k_scan2<<<1, 32>>>();
    k_scan3<<<NB_SCAN, 1024>>>();
    k_scatter<<<(ET + 255) / 256, 256>>>(ei);

    k_softmax1<<<(N_NODES * 32 + 255) / 256, 256>>>();
    k_agg1<<<N_NODES, H1 * 32>>>(b1);

    {
        dim3 g(F2 / GBN, (N_NODES + GBM - 1) / GBM);
        gemm_tf32<1><<<g, 256, GEMM_SMEM>>>(att_src2, att_dst2);
    }
    k_softmax2<<<(N_BBOX * 32 + 255) / 256, 256>>>(bbox);
    k_agg2<<<N_BBOX, H2 * 32>>>(bbox, b2, out);
}